// round 14
// baseline (speedup 1.0000x reference)
// v11: CTA 128x256, warp tile 64x64 — cut smem bytes/FLOP, tensor-bound GEMM.
#include <cuda_runtime.h>
#include <cuda_fp16.h>
#include <cstdint>

#define NB      32768      // batch
#define HH      512        // hidden
#define MDV     8          // meta embed dim
#define CDV     1024       // classifier dim
#define KIN     532        // H + 20
#define KPAD    576        // padded K
#define EPSF    1e-6f

// GEMM tiling
#define BM      128
#define BN      256
#define BK      64
#define NSTAGE  2
#define KCHUNKS 9          // 576 / 64

#define TSTRIDE 72                        // fp16 elems per smem row (144 B)
#define A_TILE_BYTES (BM * TSTRIDE * 2)   // 18432
#define B_TILE_BYTES (BN * TSTRIDE * 2)   // 36864
#define STAGE_BYTES  (A_TILE_BYTES + B_TILE_BYTES)   // 55296
#define SMEM_GEMM    (NSTAGE * STAGE_BYTES)          // 110592

// ---- scratch (static device globals; no runtime allocation) ----
__device__ float  g_meta_feat[NB * 20];
__device__ __half g_features[(size_t)NB * CDV];
__device__ __half g_Ah[(size_t)NB * KPAD];
__device__ __half g_Wh[(size_t)CDV * KPAD];
__device__ int    g_seg_start[NB];
__device__ int    g_seg_end[NB];

// ---------------------------------------------------------------------------
// PTX helpers
// ---------------------------------------------------------------------------
__device__ __forceinline__ uint32_t smem_u32(const void* p) {
    uint32_t a;
    asm("{ .reg .u64 t; cvta.to.shared.u64 t, %1; cvt.u32.u64 %0, t; }"
        : "=r"(a) : "l"(p));
    return a;
}

__device__ __forceinline__ void cp16(uint32_t s, const void* g) {
    asm volatile("cp.async.cg.shared.global [%0], [%1], 16;" :: "r"(s), "l"(g));
}
__device__ __forceinline__ void cp_commit() {
    asm volatile("cp.async.commit_group;" ::: "memory");
}
template <int N>
__device__ __forceinline__ void cp_wait() {
    asm volatile("cp.async.wait_group %0;" :: "n"(N) : "memory");
}

__device__ __forceinline__ void ldsm4(uint32_t* r, uint32_t a) {
    asm volatile("ldmatrix.sync.aligned.m8n8.x4.shared.b16 {%0,%1,%2,%3}, [%4];"
                 : "=r"(r[0]), "=r"(r[1]), "=r"(r[2]), "=r"(r[3]) : "r"(a));
}

__device__ __forceinline__ void mma16816(float* c, const uint32_t* a, const uint32_t* b) {
    asm volatile("mma.sync.aligned.m16n8k16.row.col.f32.f16.f16.f32 "
                 "{%0,%1,%2,%3}, {%4,%5,%6,%7}, {%8,%9}, {%0,%1,%2,%3};"
                 : "+f"(c[0]), "+f"(c[1]), "+f"(c[2]), "+f"(c[3])
                 : "r"(a[0]), "r"(a[1]), "r"(a[2]), "r"(a[3]),
                   "r"(b[0]), "r"(b[1]));
}

// ---------------------------------------------------------------------------
// K0: segment boundary scatter over sorted cat_seg.
// ---------------------------------------------------------------------------
__global__ void __launch_bounds__(256)
seg_bounds_kernel(const int* __restrict__ cat_seg, int ncat) {
    int i = blockIdx.x * 256 + threadIdx.x;
    if (i >= ncat) return;
    int s = cat_seg[i];
    if (i == 0 || cat_seg[i - 1] != s) g_seg_start[s] = i;
    if (i == ncat - 1 || cat_seg[i + 1] != s) g_seg_end[s] = i + 1;
}

// ---------------------------------------------------------------------------
// K1: meta path. One thread per example; segment bounds precomputed.
// ---------------------------------------------------------------------------
__global__ void meta_kernel(const float* __restrict__ meta_table,
                            const float* __restrict__ conv_w,
                            const float* __restrict__ conv_b,
                            const int*   __restrict__ meta_ids,
                            const int*   __restrict__ cat_ids) {
    __shared__ float s_cw[90];
    __shared__ float s_cb[5];
    if (threadIdx.x < 90) s_cw[threadIdx.x] = conv_w[threadIdx.x];
    if (threadIdx.x < 5)  s_cb[threadIdx.x] = conv_b[threadIdx.x];
    __syncthreads();

    int b = blockIdx.x * blockDim.x + threadIdx.x;
    if (b >= NB) return;

    int start = g_seg_start[b];
    int end   = g_seg_end[b];

    float mm[6][8];
    float sum[8];
#pragma unroll
    for (int d = 0; d < 8; d++) sum[d] = 0.f;
    for (int j = start; j < end; j++) {
        int id = cat_ids[j];
        const float* row = meta_table + (size_t)id * MDV;
#pragma unroll
        for (int d = 0; d < 8; d++) sum[d] += __ldg(row + d);
    }
    float cnt = fmaxf((float)(end - start), 1.f);
    float rc = 1.f / cnt;
#pragma unroll
    for (int d = 0; d < 8; d++) mm[0][d] = sum[d] * rc;

#pragma unroll
    for (int r = 0; r < 5; r++) {
        int id = meta_ids[b * 5 + r];
        const float* row = meta_table + (size_t)id * MDV;
#pragma unroll
        for (int d = 0; d < 8; d++) mm[r + 1][d] = __ldg(row + d);
    }

    float mf[20];
#pragma unroll
    for (int o = 0; o < 5; o++) {
        float cv[6];
#pragma unroll
        for (int t = 0; t < 6; t++) {
            float acc = s_cb[o];
#pragma unroll
            for (int i = 0; i < 6; i++)
#pragma unroll
                for (int k = 0; k < 3; k++)
                    acc = fmaf(s_cw[(o * 6 + i) * 3 + k], mm[i][t + k], acc);
            cv[t] = fmaxf(acc, 0.f);
        }
#pragma unroll
        for (int t = 0; t < 4; t++)
            mf[o * 4 + t] = fmaxf(fmaxf(cv[t], cv[t + 1]), cv[t + 2]);
    }
#pragma unroll
    for (int q = 0; q < 20; q++) g_meta_feat[b * 20 + q] = mf[q];
}

// ---------------------------------------------------------------------------
// K2: LN1(concat(encode, meta_feat)) -> fp16 rows [NB][KPAD] (zero-padded).
// ---------------------------------------------------------------------------
__global__ void __launch_bounds__(256)
prep_kernel(const float* __restrict__ encode,
            const float* __restrict__ ln1_g,
            const float* __restrict__ ln1_b) {
    const int lane = threadIdx.x & 31;
    const int wid  = threadIdx.x >> 5;
    const int r    = blockIdx.x * 8 + wid;

    float x[18];
    float s = 0.f, s2 = 0.f;
#pragma unroll
    for (int q = 0; q < 18; q++) {
        int k = lane + 32 * q;
        float v = 0.f;
        if (k < KIN)
            v = (k < HH) ? encode[(size_t)r * HH + k]
                         : g_meta_feat[r * 20 + (k - HH)];
        x[q] = v;
        s += v; s2 = fmaf(v, v, s2);
    }
#pragma unroll
    for (int o = 16; o; o >>= 1) {
        s  += __shfl_xor_sync(0xffffffffu, s,  o);
        s2 += __shfl_xor_sync(0xffffffffu, s2, o);
    }
    float mu  = s * (1.f / (float)KIN);
    float var = fmaxf(s2 * (1.f / (float)KIN) - mu * mu, 0.f) + EPSF;
    float rinv = rsqrtf(var);
    rinv = rinv * (1.5f - 0.5f * var * rinv * rinv);

    __half* ah = g_Ah + (size_t)r * KPAD;
#pragma unroll
    for (int q = 0; q < 18; q++) {
        int k = lane + 32 * q;
        float v = 0.f;
        if (k < KIN)
            v = fmaf(__ldg(ln1_g + k), (x[q] - mu) * rinv, __ldg(ln1_b + k));
        ah[k] = __float2half_rn(v);
    }
}

// ---------------------------------------------------------------------------
// K3: W -> fp16 [CDV][KPAD] + init of segment-bounds arrays (32768 thr = NB).
// ---------------------------------------------------------------------------
__global__ void __launch_bounds__(256)
wconv_kernel(const float* __restrict__ mlp1_w) {
    const int t = blockIdx.x * 256 + threadIdx.x;    // 0..32767
    g_seg_start[t] = 0;
    g_seg_end[t]   = 0;

    const int lane = threadIdx.x & 31;
    const int wid  = threadIdx.x >> 5;
    const int r    = blockIdx.x * 8 + wid;           // 0..1023 over 128 blocks
    if (r < CDV) {
        __half* wh = g_Wh + (size_t)r * KPAD;
        for (int k = lane; k < KPAD; k += 32) {
            float v = (k < KIN) ? mlp1_w[(size_t)r * KIN + k] : 0.f;
            wh[k] = __float2half_rn(v);
        }
    }
}

// ---------------------------------------------------------------------------
// K4: HMMA GEMM1: features = relu(A @ W^T + b), single-pass fp16.
// CTA 128x256, warp tile 64x64 (8 warps, 2x4), BK=64, 2-stage cp.async,
// one barrier per chunk.
// ---------------------------------------------------------------------------
__global__ void __launch_bounds__(256, 1)
gemm1_hmma(const float* __restrict__ mlp1_b) {
    extern __shared__ char smem[];
    const uint32_t sbase = smem_u32(smem);
    const int tid  = threadIdx.x;
    const int lane = tid & 31;
    const int wid  = tid >> 5;
    const int wm   = wid >> 2;          // 0..1 : 64-row slice
    const int wn   = wid & 3;           // 0..3 : 64-col slice
    const int mt   = blockIdx.x >> 2;
    const int nt   = blockIdx.x & 3;
    const int row0 = mt * BM;
    const int n0   = nt * BN;

    const __half* gA = g_Ah + (size_t)row0 * KPAD;
    const __half* gB = g_Wh + (size_t)n0   * KPAD;

    // stage loader: A 128 rows + B 256 rows, 8 segs(16B) each = 3072 cp16
    auto load_stage = [&](int c, int st) {
        const int k0 = c * BK;
        const uint32_t sst = sbase + st * STAGE_BYTES;
#pragma unroll
        for (int h = 0; h < 4; h++) {
            int idx = tid + h * 256;              // 0..1023 : A tile
            int row = idx >> 3, seg = idx & 7;
            cp16(sst + (row * TSTRIDE + seg * 8) * 2,
                 gA + (size_t)row * KPAD + k0 + seg * 8);
        }
#pragma unroll
        for (int h = 0; h < 8; h++) {
            int idx = tid + h * 256;              // 0..2047 : B tile
            int row = idx >> 3, seg = idx & 7;
            cp16(sst + A_TILE_BYTES + (row * TSTRIDE + seg * 8) * 2,
                 gB + (size_t)row * KPAD + k0 + seg * 8);
        }
    };

    float acc[4][8][4];
#pragma unroll
    for (int i = 0; i < 4; i++)
#pragma unroll
        for (int j = 0; j < 8; j++)
#pragma unroll
            for (int e = 0; e < 4; e++) acc[i][j][e] = 0.f;

    load_stage(0, 0); cp_commit();

    // lane-dependent smem offsets (bytes)
    const uint32_t a_off0 = ((wm * 64 + (lane & 15)) * TSTRIDE + (lane >> 4) * 8) * 2;
    const uint32_t b_off0 = ((wn * 64 + ((lane >> 4) << 3) + (lane & 7)) * TSTRIDE
                             + (lane & 8)) * 2;

    for (int c = 0; c < KCHUNKS; c++) {
        // ACQUIRE: only group c can be in flight here; drain it, then barrier
        // => all threads' stage-c bytes visible AND all warps done with c-1.
        cp_wait<0>();
        __syncthreads();
        // prefetch c+1 into the slot chunk c-1 used (safe post-barrier)
        if (c + 1 < KCHUNKS) { load_stage(c + 1, (c + 1) & 1); cp_commit(); }

        const uint32_t aT = sbase + (c & 1) * STAGE_BYTES;
        const uint32_t bT = aT + A_TILE_BYTES;

#pragma unroll
        for (int ks = 0; ks < 4; ks++) {
            uint32_t af[4][4];
#pragma unroll
            for (int mf = 0; mf < 4; mf++)
                ldsm4(af[mf], aT + a_off0 + (mf * 16 * TSTRIDE + ks * 16) * 2);
#pragma unroll
            for (int nf2 = 0; nf2 < 4; nf2++) {
                uint32_t bf[4];
                ldsm4(bf, bT + b_off0 + (nf2 * 16 * TSTRIDE + ks * 16) * 2);
#pragma unroll
                for (int mf = 0; mf < 4; mf++) {
                    mma16816(acc[mf][2 * nf2 + 0], af[mf], bf + 0);
                    mma16816(acc[mf][2 * nf2 + 1], af[mf], bf + 2);
                }
            }
        }
    }

    // ---- epilogue: bias + relu, fp16 stores ----
    const int l4 = lane >> 2, l2 = lane & 3;
#pragma unroll
    for (int mf = 0; mf < 4; mf++) {
        int row = row0 + wm * 64 + mf * 16 + l4;
#pragma unroll
        for (int nf = 0; nf < 8; nf++) {
            int col = n0 + wn * 64 + nf * 8 + 2 * l2;
            float2 bb = *(const float2*)(mlp1_b + col);
            __half2 v0 = __floats2half2_rn(fmaxf(acc[mf][nf][0] + bb.x, 0.f),
                                           fmaxf(acc[mf][nf][1] + bb.y, 0.f));
            __half2 v1 = __floats2half2_rn(fmaxf(acc[mf][nf][2] + bb.x, 0.f),
                                           fmaxf(acc[mf][nf][3] + bb.y, 0.f));
            *(__half2*)(g_features + (size_t)row * CDV + col)       = v0;
            *(__half2*)(g_features + (size_t)(row + 8) * CDV + col) = v1;
        }
    }
}

// ---------------------------------------------------------------------------
// K5: LN2 + GEMM2 (1024 -> 6) + out_b + normalized credit biases.
// ---------------------------------------------------------------------------
__global__ void __launch_bounds__(256)
head_kernel(const float* __restrict__ credit,
            const float* __restrict__ ln2_g,
            const float* __restrict__ ln2_b,
            const float* __restrict__ out_w,
            const float* __restrict__ out_b,
            float* __restrict__ out) {
    __shared__ float s_w[6 * CDV];
    __shared__ float s_g[CDV];
    __shared__ float s_b[CDV];
    __shared__ float s_ob[6];
    for (int i = threadIdx.x; i < 6 * CDV; i += 256) s_w[i] = out_w[i];
    for (int i = threadIdx.x; i < CDV; i += 256) { s_g[i] = ln2_g[i]; s_b[i] = ln2_b[i]; }
    if (threadIdx.x < 6) s_ob[threadIdx.x] = out_b[threadIdx.x];
    __syncthreads();

    const int lane = threadIdx.x & 31;
    const int w    = threadIdx.x >> 5;

    for (int rr = 0; rr < 4; rr++) {
        const int r = blockIdx.x * 32 + w * 4 + rr;

        const __half2* f = (const __half2*)(g_features + (size_t)r * CDV);
        float2 x[16];
        float s = 0.f, s2 = 0.f;
#pragma unroll
        for (int q = 0; q < 16; q++) {
            x[q] = __half22float2(f[lane + 32 * q]);
            s += x[q].x + x[q].y;
            s2 = fmaf(x[q].x, x[q].x, fmaf(x[q].y, x[q].y, s2));
        }
#pragma unroll
        for (int o = 16; o; o >>= 1) {
            s  += __shfl_xor_sync(0xffffffffu, s,  o);
            s2 += __shfl_xor_sync(0xffffffffu, s2, o);
        }
        float mu  = s * (1.f / (float)CDV);
        float var = fmaxf(s2 * (1.f / (float)CDV) - mu * mu, 0.f) + EPSF;
        float rinv = rsqrtf(var);
        rinv = rinv * (1.5f - 0.5f * var * rinv * rinv);

        float acc[6] = {0.f, 0.f, 0.f, 0.f, 0.f, 0.f};
#pragma unroll
        for (int q = 0; q < 16; q++) {
            int k = 2 * (lane + 32 * q);
            float zn0 = fmaf(s_g[k],     (x[q].x - mu) * rinv, s_b[k]);
            float zn1 = fmaf(s_g[k + 1], (x[q].y - mu) * rinv, s_b[k + 1]);
#pragma unroll
            for (int o = 0; o < 6; o++) {
                acc[o] = fmaf(zn0, s_w[o * CDV + k],     acc[o]);
                acc[o] = fmaf(zn1, s_w[o * CDV + k + 1], acc[o]);
            }
        }
#pragma unroll
        for (int o = 0; o < 6; o++)
#pragma unroll
            for (int d = 16; d; d >>= 1)
                acc[o] += __shfl_xor_sync(0xffffffffu, acc[o], d);

        if (lane == 0) {
            float cvals[6], cs = 0.f;
#pragma unroll
            for (int o = 0; o < 6; o++) { cvals[o] = credit[r * 6 + o]; cs += cvals[o]; }
            float inv = (cs > 0.f) ? (1.f / cs) : 0.f;
#pragma unroll
            for (int o = 0; o < 6; o++) {
                float bias = (cs > 0.f) ? cvals[o] * inv : (1.f / 6.f);
                out[r * 6 + o] = acc[o] + s_ob[o] + bias;
            }
        }
    }
}

// ---------------------------------------------------------------------------
extern "C" void kernel_launch(void* const* d_in, const int* in_sizes, int n_in,
                              void* d_out, int out_size) {
    const float* encode     = (const float*)d_in[0];
    const float* credit_vec = (const float*)d_in[1];
    const float* meta_table = (const float*)d_in[2];
    const float* conv_w     = (const float*)d_in[3];
    const float* conv_b     = (const float*)d_in[4];
    const float* ln1_g      = (const float*)d_in[5];
    const float* ln1_b      = (const float*)d_in[6];
    const float* mlp1_w     = (const float*)d_in[7];
    const float* mlp1_b     = (const float*)d_in[8];
    const float* ln2_g      = (const float*)d_in[9];
    const float* ln2_b      = (const float*)d_in[10];
    const float* out_w      = (const float*)d_in[11];
    const float* out_b      = (const float*)d_in[12];
    const int*   meta_ids   = (const int*)d_in[13];
    const int*   cat_ids    = (const int*)d_in[14];
    const int*   cat_seg    = (const int*)d_in[15];
    float*       out        = (float*)d_out;
    const int    ncat       = in_sizes[14];

    cudaFuncSetAttribute(gemm1_hmma,
                         cudaFuncAttributeMaxDynamicSharedMemorySize, SMEM_GEMM);

    wconv_kernel<<<NB / 256, 256>>>(mlp1_w);        // also zeroes seg bounds
    seg_bounds_kernel<<<(ncat + 255) / 256, 256>>>(cat_seg, ncat);
    meta_kernel<<<NB / 256, 256>>>(meta_table, conv_w, conv_b,
                                   meta_ids, cat_ids);
    prep_kernel<<<NB / 8, 256>>>(encode, ln1_g, ln1_b);
    gemm1_hmma<<<(NB / BM) * (CDV / BN), 256, SMEM_GEMM>>>(mlp1_b);
    head_kernel<<<NB / 32, 256>>>(credit_vec, ln2_g, ln2_b, out_w, out_b, out);
}

// round 16
// speedup vs baseline: 1.0551x; 1.0551x over previous
// v12: revert GEMM to v10 (best); fuse meta path into prep (5 launches).
#include <cuda_runtime.h>
#include <cuda_fp16.h>
#include <cstdint>

#define NB      32768      // batch
#define HH      512        // hidden
#define MDV     8          // meta embed dim
#define CDV     1024       // classifier dim
#define KIN     532        // H + 20
#define KPAD    576        // padded K
#define EPSF    1e-6f

// GEMM tiling (v10 proven config)
#define BM      128
#define BN      128
#define BK      64
#define NSTAGE  3
#define KCHUNKS 9          // 576 / 64

#define TSTRIDE 72                       // fp16 elems per smem row (144 B)
#define TILE_BYTES  (128 * TSTRIDE * 2)  // 18432
#define STAGE_BYTES (2 * TILE_BYTES)     // 36864 (A, W)
#define SMEM_GEMM   (NSTAGE * STAGE_BYTES) // 110592

// ---- scratch (static device globals; no runtime allocation) ----
__device__ __half g_features[(size_t)NB * CDV];
__device__ __half g_Ah[(size_t)NB * KPAD];
__device__ __half g_Wh[(size_t)CDV * KPAD];
__device__ int    g_seg_start[NB];
__device__ int    g_seg_end[NB];

// ---------------------------------------------------------------------------
// PTX helpers
// ---------------------------------------------------------------------------
__device__ __forceinline__ uint32_t smem_u32(const void* p) {
    uint32_t a;
    asm("{ .reg .u64 t; cvta.to.shared.u64 t, %1; cvt.u32.u64 %0, t; }"
        : "=r"(a) : "l"(p));
    return a;
}

__device__ __forceinline__ void cp16(uint32_t s, const void* g) {
    asm volatile("cp.async.cg.shared.global [%0], [%1], 16;" :: "r"(s), "l"(g));
}
__device__ __forceinline__ void cp_commit() {
    asm volatile("cp.async.commit_group;" ::: "memory");
}
template <int N>
__device__ __forceinline__ void cp_wait() {
    asm volatile("cp.async.wait_group %0;" :: "n"(N) : "memory");
}

__device__ __forceinline__ void ldsm4(uint32_t* r, uint32_t a) {
    asm volatile("ldmatrix.sync.aligned.m8n8.x4.shared.b16 {%0,%1,%2,%3}, [%4];"
                 : "=r"(r[0]), "=r"(r[1]), "=r"(r[2]), "=r"(r[3]) : "r"(a));
}

__device__ __forceinline__ void mma16816(float* c, const uint32_t* a, const uint32_t* b) {
    asm volatile("mma.sync.aligned.m16n8k16.row.col.f32.f16.f16.f32 "
                 "{%0,%1,%2,%3}, {%4,%5,%6,%7}, {%8,%9}, {%0,%1,%2,%3};"
                 : "+f"(c[0]), "+f"(c[1]), "+f"(c[2]), "+f"(c[3])
                 : "r"(a[0]), "r"(a[1]), "r"(a[2]), "r"(a[3]),
                   "r"(b[0]), "r"(b[1]));
}

// ---------------------------------------------------------------------------
// K0: segment boundary scatter over sorted cat_seg.
// ---------------------------------------------------------------------------
__global__ void __launch_bounds__(256)
seg_bounds_kernel(const int* __restrict__ cat_seg, int ncat) {
    int i = blockIdx.x * 256 + threadIdx.x;
    if (i >= ncat) return;
    int s = cat_seg[i];
    if (i == 0 || cat_seg[i - 1] != s) g_seg_start[s] = i;
    if (i == ncat - 1 || cat_seg[i + 1] != s) g_seg_end[s] = i + 1;
}

// ---------------------------------------------------------------------------
// K1: W -> fp16 [CDV][KPAD] + init of segment-bounds arrays (32768 thr = NB).
// ---------------------------------------------------------------------------
__global__ void __launch_bounds__(256)
wconv_kernel(const float* __restrict__ mlp1_w) {
    const int t = blockIdx.x * 256 + threadIdx.x;    // 0..32767
    g_seg_start[t] = 0;
    g_seg_end[t]   = 0;

    const int lane = threadIdx.x & 31;
    const int wid  = threadIdx.x >> 5;
    const int r    = blockIdx.x * 8 + wid;           // 0..1023 over 128 blocks
    if (r < CDV) {
        __half* wh = g_Wh + (size_t)r * KPAD;
        for (int k = lane; k < KPAD; k += 32) {
            float v = (k < KIN) ? mlp1_w[(size_t)r * KIN + k] : 0.f;
            wh[k] = __float2half_rn(v);
        }
    }
}

// ---------------------------------------------------------------------------
// K2 (fused meta + prep): per-warp meta features (segment mean -> conv ->
// relu -> maxpool), then LN1(concat(encode, meta_feat)) -> fp16 rows.
// One warp per example row; 8 rows per block.
// ---------------------------------------------------------------------------
__global__ void __launch_bounds__(256)
prep_kernel(const float* __restrict__ encode,
            const float* __restrict__ ln1_g,
            const float* __restrict__ ln1_b,
            const float* __restrict__ meta_table,
            const float* __restrict__ conv_w,
            const float* __restrict__ conv_b,
            const int*   __restrict__ meta_ids,
            const int*   __restrict__ cat_ids) {
    __shared__ float s_cw[90];
    __shared__ float s_cb[5];
    __shared__ float s_mm[8][6][8];    // per-warp meta matrix
    __shared__ float s_mf[8][20];      // per-warp meta features
    if (threadIdx.x < 90) s_cw[threadIdx.x] = conv_w[threadIdx.x];
    if (threadIdx.x < 5)  s_cb[threadIdx.x] = conv_b[threadIdx.x];
    __syncthreads();

    const int lane = threadIdx.x & 31;
    const int wid  = threadIdx.x >> 5;
    const int r    = blockIdx.x * 8 + wid;

    // ---- segment mean (lane-parallel over ragged ids, shfl reduce) ----
    const int start = g_seg_start[r];
    const int end   = g_seg_end[r];
    float sum[8];
#pragma unroll
    for (int d = 0; d < 8; d++) sum[d] = 0.f;
    for (int j = start + lane; j < end; j += 32) {
        int id = cat_ids[j];
        const float* row = meta_table + (size_t)id * MDV;
#pragma unroll
        for (int d = 0; d < 8; d++) sum[d] += __ldg(row + d);
    }
#pragma unroll
    for (int d = 0; d < 8; d++)
#pragma unroll
        for (int o = 16; o; o >>= 1)
            sum[d] += __shfl_xor_sync(0xffffffffu, sum[d], o);
    float rc = 1.f / fmaxf((float)(end - start), 1.f);
    if (lane < 8) s_mm[wid][0][lane] = sum[lane] * rc;

    // ---- 5 gathered meta embeds: 40 values across lanes ----
    for (int idx = lane; idx < 40; idx += 32) {
        int row = idx >> 3, d = idx & 7;
        int id = meta_ids[r * 5 + row];
        s_mm[wid][row + 1][d] = __ldg(meta_table + (size_t)id * MDV + d);
    }
    __syncwarp();

    // ---- conv(6->5,k=3) + relu + maxpool3: 20 outputs on lanes 0..19 ----
    if (lane < 20) {
        int o = lane >> 2, t0 = lane & 3;
        float best = 0.f;   // relu(conv) >= 0, so max over relu >= 0
        bool first = true;
#pragma unroll
        for (int tt = 0; tt < 3; tt++) {
            int t = t0 + tt;
            float acc = s_cb[o];
#pragma unroll
            for (int i = 0; i < 6; i++)
#pragma unroll
                for (int k = 0; k < 3; k++)
                    acc = fmaf(s_cw[(o * 6 + i) * 3 + k], s_mm[wid][i][t + k], acc);
            acc = fmaxf(acc, 0.f);
            best = first ? acc : fmaxf(best, acc);
            first = false;
        }
        s_mf[wid][lane] = best;
    }
    __syncwarp();

    // ---- LN1 over [encode | meta_feat], write fp16 padded row ----
    float x[18];
    float s = 0.f, s2 = 0.f;
#pragma unroll
    for (int q = 0; q < 18; q++) {
        int k = lane + 32 * q;
        float v = 0.f;
        if (k < KIN)
            v = (k < HH) ? encode[(size_t)r * HH + k] : s_mf[wid][k - HH];
        x[q] = v;
        s += v; s2 = fmaf(v, v, s2);
    }
#pragma unroll
    for (int o = 16; o; o >>= 1) {
        s  += __shfl_xor_sync(0xffffffffu, s,  o);
        s2 += __shfl_xor_sync(0xffffffffu, s2, o);
    }
    float mu  = s * (1.f / (float)KIN);
    float var = fmaxf(s2 * (1.f / (float)KIN) - mu * mu, 0.f) + EPSF;
    float rinv = rsqrtf(var);
    rinv = rinv * (1.5f - 0.5f * var * rinv * rinv);

    __half* ah = g_Ah + (size_t)r * KPAD;
#pragma unroll
    for (int q = 0; q < 18; q++) {
        int k = lane + 32 * q;
        float v = 0.f;
        if (k < KIN)
            v = fmaf(__ldg(ln1_g + k), (x[q] - mu) * rinv, __ldg(ln1_b + k));
        ah[k] = __float2half_rn(v);
    }
}

// ---------------------------------------------------------------------------
// K3: HMMA GEMM1 (v10 proven): features = relu(A @ W^T + b), fp16.
// CTA 128x128, BK=64, 3-stage cp.async, one barrier per chunk (wait->sync),
// 2 CTAs/SM.
// ---------------------------------------------------------------------------
__global__ void __launch_bounds__(256, 2)
gemm1_hmma(const float* __restrict__ mlp1_b) {
    extern __shared__ char smem[];
    const uint32_t sbase = smem_u32(smem);
    const int tid  = threadIdx.x;
    const int lane = tid & 31;
    const int wid  = tid >> 5;
    const int wm   = wid >> 1;          // 0..3 : 32-row slice
    const int wn   = wid & 1;           // 0..1 : 64-col slice
    const int mt   = blockIdx.x >> 3;
    const int nt   = blockIdx.x & 7;
    const int row0 = mt * BM;
    const int n0   = nt * BN;

    const __half* gsrc[2] = {
        g_Ah + (size_t)row0 * KPAD,
        g_Wh + (size_t)n0   * KPAD };

    auto load_stage = [&](int c, int st) {
        const int k0 = c * BK;
        const uint32_t sst = sbase + st * STAGE_BYTES;
#pragma unroll
        for (int t = 0; t < 2; t++) {
#pragma unroll
            for (int h = 0; h < 4; h++) {
                int idx = tid + h * 256;          // 0..1023
                int row = idx >> 3, seg = idx & 7;
                cp16(sst + t * TILE_BYTES + (row * TSTRIDE + seg * 8) * 2,
                     gsrc[t] + (size_t)row * KPAD + k0 + seg * 8);
            }
        }
    };

    float acc[2][8][4];
#pragma unroll
    for (int i = 0; i < 2; i++)
#pragma unroll
        for (int j = 0; j < 8; j++)
#pragma unroll
            for (int e = 0; e < 4; e++) acc[i][j][e] = 0.f;

    load_stage(0, 0); cp_commit();
    load_stage(1, 1); cp_commit();

    const uint32_t a_off0 = ((wm * 32 + (lane & 15)) * TSTRIDE + (lane >> 4) * 8) * 2;
    const uint32_t b_off0 = ((wn * 64 + ((lane >> 4) << 3) + (lane & 7)) * TSTRIDE
                             + (lane & 8)) * 2;

    for (int c = 0; c < KCHUNKS; c++) {
        // ACQUIRE: my stage-c group done, then barrier => all threads' stage-c
        // copies visible, and every warp has finished chunk c-1's MMAs.
        cp_wait<NSTAGE - 2>();
        __syncthreads();
        if (c + 2 < KCHUNKS) load_stage(c + 2, (c + 2) % NSTAGE);
        cp_commit();

        const uint32_t aT = sbase + (c % NSTAGE) * STAGE_BYTES;
        const uint32_t bT = aT + TILE_BYTES;

#pragma unroll
        for (int ks = 0; ks < 4; ks++) {
            uint32_t af[2][4], bf[4][4];
#pragma unroll
            for (int mf = 0; mf < 2; mf++)
                ldsm4(af[mf], aT + a_off0 + (mf * 16 * TSTRIDE + ks * 16) * 2);
#pragma unroll
            for (int nf2 = 0; nf2 < 4; nf2++)
                ldsm4(bf[nf2], bT + b_off0 + (nf2 * 16 * TSTRIDE + ks * 16) * 2);
#pragma unroll
            for (int nf2 = 0; nf2 < 4; nf2++)
#pragma unroll
                for (int mf = 0; mf < 2; mf++) {
                    mma16816(acc[mf][2 * nf2 + 0], af[mf], bf[nf2] + 0);
                    mma16816(acc[mf][2 * nf2 + 1], af[mf], bf[nf2] + 2);
                }
        }
    }

    // ---- epilogue: bias + relu, fp16 stores ----
    const int l4 = lane >> 2, l2 = lane & 3;
#pragma unroll
    for (int mf = 0; mf < 2; mf++) {
        int row = row0 + wm * 32 + mf * 16 + l4;
#pragma unroll
        for (int nf = 0; nf < 8; nf++) {
            int col = n0 + wn * 64 + nf * 8 + 2 * l2;
            float2 bb = *(const float2*)(mlp1_b + col);
            __half2 v0 = __floats2half2_rn(fmaxf(acc[mf][nf][0] + bb.x, 0.f),
                                           fmaxf(acc[mf][nf][1] + bb.y, 0.f));
            __half2 v1 = __floats2half2_rn(fmaxf(acc[mf][nf][2] + bb.x, 0.f),
                                           fmaxf(acc[mf][nf][3] + bb.y, 0.f));
            *(__half2*)(g_features + (size_t)row * CDV + col)       = v0;
            *(__half2*)(g_features + (size_t)(row + 8) * CDV + col) = v1;
        }
    }
}

// ---------------------------------------------------------------------------
// K4: LN2 + GEMM2 (1024 -> 6) + out_b + normalized credit biases.
// 32 rows per block (warp x 4 sequential) to amortize smem weight preload.
// ---------------------------------------------------------------------------
__global__ void __launch_bounds__(256)
head_kernel(const float* __restrict__ credit,
            const float* __restrict__ ln2_g,
            const float* __restrict__ ln2_b,
            const float* __restrict__ out_w,
            const float* __restrict__ out_b,
            float* __restrict__ out) {
    __shared__ float s_w[6 * CDV];
    __shared__ float s_g[CDV];
    __shared__ float s_b[CDV];
    __shared__ float s_ob[6];
    for (int i = threadIdx.x; i < 6 * CDV; i += 256) s_w[i] = out_w[i];
    for (int i = threadIdx.x; i < CDV; i += 256) { s_g[i] = ln2_g[i]; s_b[i] = ln2_b[i]; }
    if (threadIdx.x < 6) s_ob[threadIdx.x] = out_b[threadIdx.x];
    __syncthreads();

    const int lane = threadIdx.x & 31;
    const int w    = threadIdx.x >> 5;

    for (int rr = 0; rr < 4; rr++) {
        const int r = blockIdx.x * 32 + w * 4 + rr;

        const __half2* f = (const __half2*)(g_features + (size_t)r * CDV);
        float2 x[16];
        float s = 0.f, s2 = 0.f;
#pragma unroll
        for (int q = 0; q < 16; q++) {
            x[q] = __half22float2(f[lane + 32 * q]);
            s += x[q].x + x[q].y;
            s2 = fmaf(x[q].x, x[q].x, fmaf(x[q].y, x[q].y, s2));
        }
#pragma unroll
        for (int o = 16; o; o >>= 1) {
            s  += __shfl_xor_sync(0xffffffffu, s,  o);
            s2 += __shfl_xor_sync(0xffffffffu, s2, o);
        }
        float mu  = s * (1.f / (float)CDV);
        float var = fmaxf(s2 * (1.f / (float)CDV) - mu * mu, 0.f) + EPSF;
        float rinv = rsqrtf(var);
        rinv = rinv * (1.5f - 0.5f * var * rinv * rinv);

        float acc[6] = {0.f, 0.f, 0.f, 0.f, 0.f, 0.f};
#pragma unroll
        for (int q = 0; q < 16; q++) {
            int k = 2 * (lane + 32 * q);
            float zn0 = fmaf(s_g[k],     (x[q].x - mu) * rinv, s_b[k]);
            float zn1 = fmaf(s_g[k + 1], (x[q].y - mu) * rinv, s_b[k + 1]);
#pragma unroll
            for (int o = 0; o < 6; o++) {
                acc[o] = fmaf(zn0, s_w[o * CDV + k],     acc[o]);
                acc[o] = fmaf(zn1, s_w[o * CDV + k + 1], acc[o]);
            }
        }
#pragma unroll
        for (int o = 0; o < 6; o++)
#pragma unroll
            for (int d = 16; d; d >>= 1)
                acc[o] += __shfl_xor_sync(0xffffffffu, acc[o], d);

        if (lane == 0) {
            float cvals[6], cs = 0.f;
#pragma unroll
            for (int o = 0; o < 6; o++) { cvals[o] = credit[r * 6 + o]; cs += cvals[o]; }
            float inv = (cs > 0.f) ? (1.f / cs) : 0.f;
#pragma unroll
            for (int o = 0; o < 6; o++) {
                float bias = (cs > 0.f) ? cvals[o] * inv : (1.f / 6.f);
                out[r * 6 + o] = acc[o] + s_ob[o] + bias;
            }
        }
    }
}

// ---------------------------------------------------------------------------
extern "C" void kernel_launch(void* const* d_in, const int* in_sizes, int n_in,
                              void* d_out, int out_size) {
    const float* encode     = (const float*)d_in[0];
    const float* credit_vec = (const float*)d_in[1];
    const float* meta_table = (const float*)d_in[2];
    const float* conv_w     = (const float*)d_in[3];
    const float* conv_b     = (const float*)d_in[4];
    const float* ln1_g      = (const float*)d_in[5];
    const float* ln1_b      = (const float*)d_in[6];
    const float* mlp1_w     = (const float*)d_in[7];
    const float* mlp1_b     = (const float*)d_in[8];
    const float* ln2_g      = (const float*)d_in[9];
    const float* ln2_b      = (const float*)d_in[10];
    const float* out_w      = (const float*)d_in[11];
    const float* out_b      = (const float*)d_in[12];
    const int*   meta_ids   = (const int*)d_in[13];
    const int*   cat_ids    = (const int*)d_in[14];
    const int*   cat_seg    = (const int*)d_in[15];
    float*       out        = (float*)d_out;
    const int    ncat       = in_sizes[14];

    cudaFuncSetAttribute(gemm1_hmma,
                         cudaFuncAttributeMaxDynamicSharedMemorySize, SMEM_GEMM);

    wconv_kernel<<<NB / 256, 256>>>(mlp1_w);        // W fp16 + zero seg bounds
    seg_bounds_kernel<<<(ncat + 255) / 256, 256>>>(cat_seg, ncat);
    prep_kernel<<<NB / 8, 256>>>(encode, ln1_g, ln1_b,
                                 meta_table, conv_w, conv_b,
                                 meta_ids, cat_ids);
    gemm1_hmma<<<(NB / BM) * (CDV / BN), 256, SMEM_GEMM>>>(mlp1_b);
    head_kernel<<<NB / 32, 256>>>(credit_vec, ln2_g, ln2_b, out_w, out_b, out);
}